// round 6
// baseline (speedup 1.0000x reference)
#include <cuda_runtime.h>

typedef unsigned long long ull;

#define BATCH 4
#define SEQ   4096
#define HID   512

// ---------------- scratch (no allocations allowed) ----------------
__device__ float g_Q[BATCH * SEQ * HID];            // 33.5 MB
__device__ float g_K[BATCH * SEQ * HID];            // 33.5 MB
__device__ float g_V[BATCH * SEQ * HID];            // 33.5 MB
__device__ float g_S[67108864];                     // 4*4096*4096 fp32 = 268 MB

// ---------------- packed f32x2 helpers ----------------
__device__ __forceinline__ ull pack_dup(float v) {
    unsigned u = __float_as_uint(v);
    ull d;
    asm("mov.b64 %0, {%1, %1};" : "=l"(d) : "r"(u));
    return d;
}
__device__ __forceinline__ void fma2(ull& acc, ull a, ull b) {
    asm("fma.rn.f32x2 %0, %1, %2, %3;" : "=l"(acc) : "l"(a), "l"(b), "l"(acc));
}
__device__ __forceinline__ float2 unpack2(ull v) {
    unsigned lo, hi;
    asm("mov.b64 {%0, %1}, %2;" : "=r"(lo), "=r"(hi) : "l"(v));
    return make_float2(__uint_as_float(lo), __uint_as_float(hi));
}

// ---------------- SGEMM: C[M,N] = op(A[M,K] @ B) (+bias) (*scale) ----------------
// Tiles: BM=128, BN=128, BK=16, 256 threads, per-thread 8x8 outputs as 8x4 f32x2.
// TRANSB=false: B physically [K,N]  (ldb = row stride in k)
// TRANSB=true : B physically [N,K]  (logical B[k][n] = Bphys[n][k]) -> used for Q @ K^T
constexpr int BM = 128, BN = 128, BKt = 16;
constexpr int LDSP = 132;  // padded smem row stride (floats), keeps 16B alignment

template <bool TRANSB, bool BIAS, bool SCALE>
__global__ __launch_bounds__(256) void gemm_k(
    const float* __restrict__ Ag, const float* __restrict__ Bg,
    const float* __restrict__ bias, float* __restrict__ Cg,
    int Kdim, int lda, int ldb, int ldc,
    long long sA, long long sB, long long sC, float scale)
{
    __shared__ __align__(16) float As[2][BKt][LDSP];
    __shared__ __align__(16) float Bs[2][BKt][LDSP];

    const int tid = threadIdx.x;
    const int tx = tid & 15;       // n direction (8 cols each)
    const int ty = tid >> 4;       // m direction (8 rows each)

    const long long z = blockIdx.z;
    const float* A = Ag + z * sA;
    const float* B = Bg + z * sB;
    float*       C = Cg + z * sC;

    const int m0 = blockIdx.y * BM;
    const int n0 = blockIdx.x * BN;

    // A tile load mapping: 128 rows x 16 k; thread loads 2 float4 (rows am, am+64)
    const int am = tid >> 2;          // 0..63
    const int ak = (tid & 3) << 2;    // 0,4,8,12
    // B tile load mapping
    const int bk8 = tid >> 5;         // 0..7   (!TRANSB: k row)
    const int bn4 = (tid & 31) << 2;  // 0..124 (!TRANSB: n col base, float4)
    const int bn  = tid >> 2;         // 0..63  (TRANSB: n row)
    const int bkq = (tid & 3) << 2;   // 0,4,8,12 (TRANSB: k col base)

    const int nT = Kdim / BKt;

    float4 pa0, pa1, pb0, pb1;

    auto gload = [&](int t) {
        const int k0 = t * BKt;
        pa0 = *(const float4*)&A[(size_t)(m0 + am)      * lda + k0 + ak];
        pa1 = *(const float4*)&A[(size_t)(m0 + am + 64) * lda + k0 + ak];
        if (TRANSB) {
            pb0 = *(const float4*)&B[(size_t)(n0 + bn)      * ldb + k0 + bkq];
            pb1 = *(const float4*)&B[(size_t)(n0 + bn + 64) * ldb + k0 + bkq];
        } else {
            pb0 = *(const float4*)&B[(size_t)(k0 + bk8)     * ldb + n0 + bn4];
            pb1 = *(const float4*)&B[(size_t)(k0 + bk8 + 8) * ldb + n0 + bn4];
        }
    };
    auto sstore = [&](int buf) {
        As[buf][ak + 0][am] = pa0.x;  As[buf][ak + 1][am] = pa0.y;
        As[buf][ak + 2][am] = pa0.z;  As[buf][ak + 3][am] = pa0.w;
        As[buf][ak + 0][am + 64] = pa1.x;  As[buf][ak + 1][am + 64] = pa1.y;
        As[buf][ak + 2][am + 64] = pa1.z;  As[buf][ak + 3][am + 64] = pa1.w;
        if (TRANSB) {
            Bs[buf][bkq + 0][bn] = pb0.x;  Bs[buf][bkq + 1][bn] = pb0.y;
            Bs[buf][bkq + 2][bn] = pb0.z;  Bs[buf][bkq + 3][bn] = pb0.w;
            Bs[buf][bkq + 0][bn + 64] = pb1.x;  Bs[buf][bkq + 1][bn + 64] = pb1.y;
            Bs[buf][bkq + 2][bn + 64] = pb1.z;  Bs[buf][bkq + 3][bn + 64] = pb1.w;
        } else {
            *(float4*)&Bs[buf][bk8][bn4]     = pb0;
            *(float4*)&Bs[buf][bk8 + 8][bn4] = pb1;
        }
    };

    gload(0);
    sstore(0);
    __syncthreads();

    ull acc[8][4];
#pragma unroll
    for (int i = 0; i < 8; ++i)
#pragma unroll
        for (int j = 0; j < 4; ++j) acc[i][j] = 0ull;

    int buf = 0;
    for (int t = 0; t < nT; ++t) {
        if (t + 1 < nT) gload(t + 1);

#pragma unroll
        for (int kk = 0; kk < BKt; ++kk) {
            const float4 a0 = *(const float4*)&As[buf][kk][ty * 8];
            const float4 a1 = *(const float4*)&As[buf][kk][ty * 8 + 4];
            const ull bv0 = *(const ull*)&Bs[buf][kk][tx * 8 + 0];
            const ull bv1 = *(const ull*)&Bs[buf][kk][tx * 8 + 2];
            const ull bv2 = *(const ull*)&Bs[buf][kk][tx * 8 + 4];
            const ull bv3 = *(const ull*)&Bs[buf][kk][tx * 8 + 6];
            const float ar[8] = {a0.x, a0.y, a0.z, a0.w, a1.x, a1.y, a1.z, a1.w};
#pragma unroll
            for (int i = 0; i < 8; ++i) {
                const ull ad = pack_dup(ar[i]);
                fma2(acc[i][0], ad, bv0);
                fma2(acc[i][1], ad, bv1);
                fma2(acc[i][2], ad, bv2);
                fma2(acc[i][3], ad, bv3);
            }
        }

        if (t + 1 < nT) {
            sstore(buf ^ 1);
            __syncthreads();
            buf ^= 1;
        }
    }

    // epilogue: per row, assemble two float4 stores (contiguous 8 cols)
#pragma unroll
    for (int i = 0; i < 8; ++i) {
        float* crow = C + (size_t)(m0 + ty * 8 + i) * ldc + n0 + tx * 8;
        float2 c[4];
#pragma unroll
        for (int j = 0; j < 4; ++j) {
            c[j] = unpack2(acc[i][j]);
            if (SCALE) { c[j].x *= scale; c[j].y *= scale; }
            if (BIAS) {
                c[j].x += bias[n0 + tx * 8 + 2 * j];
                c[j].y += bias[n0 + tx * 8 + 2 * j + 1];
            }
        }
        float4 o0 = make_float4(c[0].x, c[0].y, c[1].x, c[1].y);
        float4 o1 = make_float4(c[2].x, c[2].y, c[3].x, c[3].y);
        *(float4*)&crow[0] = o0;
        *(float4*)&crow[4] = o1;
    }
}

// ---------------- row softmax over 4096 columns, in place ----------------
__global__ __launch_bounds__(256) void softmax4096_k(float* __restrict__ S)
{
    const size_t row = blockIdx.x;
    float4* p = reinterpret_cast<float4*>(S + (row << 12));
    const int tid = threadIdx.x;

    float4 v[4];
#pragma unroll
    for (int r = 0; r < 4; ++r) v[r] = p[tid + (r << 8)];

    float m = v[0].x;
#pragma unroll
    for (int r = 0; r < 4; ++r) {
        m = fmaxf(m, v[r].x); m = fmaxf(m, v[r].y);
        m = fmaxf(m, v[r].z); m = fmaxf(m, v[r].w);
    }
#pragma unroll
    for (int o = 16; o > 0; o >>= 1) m = fmaxf(m, __shfl_xor_sync(0xffffffffu, m, o));

    __shared__ float red[8];
    if ((tid & 31) == 0) red[tid >> 5] = m;
    __syncthreads();
    m = red[0];
#pragma unroll
    for (int i = 1; i < 8; ++i) m = fmaxf(m, red[i]);
    __syncthreads();

    float s = 0.f;
#pragma unroll
    for (int r = 0; r < 4; ++r) {
        v[r].x = __expf(v[r].x - m); s += v[r].x;
        v[r].y = __expf(v[r].y - m); s += v[r].y;
        v[r].z = __expf(v[r].z - m); s += v[r].z;
        v[r].w = __expf(v[r].w - m); s += v[r].w;
    }
#pragma unroll
    for (int o = 16; o > 0; o >>= 1) s += __shfl_xor_sync(0xffffffffu, s, o);
    if ((tid & 31) == 0) red[tid >> 5] = s;
    __syncthreads();
    s = 0.f;
#pragma unroll
    for (int i = 0; i < 8; ++i) s += red[i];

    const float inv = 1.0f / s;
#pragma unroll
    for (int r = 0; r < 4; ++r) {
        v[r].x *= inv; v[r].y *= inv; v[r].z *= inv; v[r].w *= inv;
        p[tid + (r << 8)] = v[r];
    }
}

// ---------------- launch ----------------
extern "C" void kernel_launch(void* const* d_in, const int* in_sizes, int n_in,
                              void* d_out, int out_size)
{
    (void)in_sizes; (void)n_in; (void)out_size;
    const float* X  = (const float*)d_in[0];
    const float* Wq = (const float*)d_in[1];
    const float* bq = (const float*)d_in[2];
    const float* Wk = (const float*)d_in[3];
    const float* bk = (const float*)d_in[4];
    const float* Wv = (const float*)d_in[5];
    const float* bv = (const float*)d_in[6];
    float* out = (float*)d_out;

    float *Qp, *Kp, *Vp, *Sp;
    cudaGetSymbolAddress((void**)&Qp, g_Q);
    cudaGetSymbolAddress((void**)&Kp, g_K);
    cudaGetSymbolAddress((void**)&Vp, g_V);
    cudaGetSymbolAddress((void**)&Sp, g_S);

    const float scale = 0.04419417382415922f;  // 1/sqrt(512)
    dim3 blk(256);

    // QKV projections: M=16384, N=512, K=512; B = W stored [in,out] = [k][n]
    dim3 g1(HID / BN, (BATCH * SEQ) / BM, 1);
    gemm_k<false, true, false><<<g1, blk>>>(X, Wq, bq, Qp, HID, HID, HID, HID, 0, 0, 0, 1.f);
    gemm_k<false, true, false><<<g1, blk>>>(X, Wk, bk, Kp, HID, HID, HID, HID, 0, 0, 0, 1.f);
    gemm_k<false, true, false><<<g1, blk>>>(X, Wv, bv, Vp, HID, HID, HID, HID, 0, 0, 0, 1.f);

    // Scores = scale * Q @ K^T, per batch: M=N=4096, K=512
    dim3 g2(SEQ / BN, SEQ / BM, BATCH);
    gemm_k<true, false, true><<<g2, blk>>>(
        Qp, Kp, nullptr, Sp, HID, HID, HID, SEQ,
        (long long)SEQ * HID, (long long)SEQ * HID, (long long)SEQ * SEQ, scale);

    // Row softmax (4*4096 rows of 4096)
    softmax4096_k<<<BATCH * SEQ, blk>>>(Sp);

    // Out = P @ V, per batch: M=4096, N=512, K=4096; V is [k][n] naturally
    dim3 g3(HID / BN, SEQ / BM, BATCH);
    gemm_k<false, false, false><<<g3, blk>>>(
        Sp, Vp, nullptr, out, SEQ, SEQ, HID, HID,
        (long long)SEQ * SEQ, (long long)SEQ * HID, (long long)SEQ * HID, 1.f);
}

// round 9
// speedup vs baseline: 2.5163x; 2.5163x over previous
#include <cuda_runtime.h>
#include <cuda_bf16.h>
#include <cstdint>

typedef unsigned int u32;
typedef unsigned long long u64;

#define BATCH 4
#define SEQ   4096
#define HID   512

// ---------------- scratch (no allocations allowed) ----------------
__device__ float g_V[BATCH * SEQ * HID];                    // fp32 V (pre-transpose)
__device__ float g_S[(size_t)BATCH * SEQ * SEQ];            // fp32 scores, 268 MB
__device__ __nv_bfloat16 g_Qh[BATCH * SEQ * HID];           // Q hi plane [seq][hid]
__device__ __nv_bfloat16 g_Ql[BATCH * SEQ * HID];
__device__ __nv_bfloat16 g_Kh[BATCH * SEQ * HID];           // K hi plane [seq][hid]
__device__ __nv_bfloat16 g_Kl[BATCH * SEQ * HID];
__device__ __nv_bfloat16 g_Sh[(size_t)BATCH * SEQ * SEQ];   // P hi plane, 134 MB
__device__ __nv_bfloat16 g_Sl[(size_t)BATCH * SEQ * SEQ];   // P lo plane, 134 MB
__device__ __nv_bfloat16 g_WTh[3 * HID * HID];              // W^T hi planes [out][in]
__device__ __nv_bfloat16 g_WTl[3 * HID * HID];
__device__ __nv_bfloat16 g_VTh[BATCH * HID * SEQ];          // V^T hi planes [hid][seq]
__device__ __nv_bfloat16 g_VTl[BATCH * HID * SEQ];

// ---------------- helpers ----------------
__device__ __forceinline__ u32 smem_u32(const void* p) {
    u32 a;
    asm("{ .reg .u64 t; cvta.to.shared.u64 t, %1; cvt.u32.u64 %0, t; }" : "=r"(a) : "l"(p));
    return a;
}

#define SW128(o) ((o) ^ (((o) >> 3) & 0x70))

__device__ __forceinline__ u32 pack_bf2(__nv_bfloat16 a, __nv_bfloat16 b) {
    return (u32)__bfloat16_as_ushort(a) | ((u32)__bfloat16_as_ushort(b) << 16);
}

__device__ __forceinline__ void ldm4(u32& r0, u32& r1, u32& r2, u32& r3, u32 addr) {
    asm volatile("ldmatrix.sync.aligned.m8n8.x4.shared.b16 {%0,%1,%2,%3}, [%4];"
                 : "=r"(r0), "=r"(r1), "=r"(r2), "=r"(r3) : "r"(addr));
}

__device__ __forceinline__ void mma_bf16(float* d, const u32* a, u32 b0, u32 b1) {
    asm volatile(
        "mma.sync.aligned.m16n8k16.row.col.f32.bf16.bf16.f32 "
        "{%0,%1,%2,%3}, {%4,%5,%6,%7}, {%8,%9}, {%0,%1,%2,%3};"
        : "+f"(d[0]), "+f"(d[1]), "+f"(d[2]), "+f"(d[3])
        : "r"(a[0]), "r"(a[1]), "r"(a[2]), "r"(a[3]), "r"(b0), "r"(b1));
}

// ---------------- HMMA split-bf16 GEMM ----------------
// D[M,N] = A[M,K] @ B[N,K]^T  fp32-equivalent via 3-pass bf16 split.
// CTA tile 128x128, K-chunk 64 (SW128 128B rows), double-buffered.
// A: fp32 split on the fly when !APRE, else pre-split hi/lo planes.
// B: always pre-split hi/lo planes (K-major).
// EPI: 0 = fp32 + bias, 1 = fp32 * scale, 2 = split hi/lo planes + bias, 3 = fp32
static constexpr int TGEMM_SMEM = 1024 + 8 * 16384;   // pad + 2 bufs x 4 tiles x 16KB

template <bool APRE, int EPI>
__global__ __launch_bounds__(256, 1) void tgemm(
    const float* __restrict__ Af,
    const __nv_bfloat16* __restrict__ Ah, const __nv_bfloat16* __restrict__ Al,
    const __nv_bfloat16* __restrict__ Bh, const __nv_bfloat16* __restrict__ Bl,
    const float* __restrict__ bias,
    float* __restrict__ Cf,
    __nv_bfloat16* __restrict__ Ch, __nv_bfloat16* __restrict__ Cl,
    int Kdim, int lda, int ldb, int ldc,
    long long sA, long long sB, long long sC, float scale)
{
    extern __shared__ char dsm[];

    const int tid = threadIdx.x;
    const long long z = blockIdx.z;
    const int m0 = blockIdx.y * 128, n0 = blockIdx.x * 128;

    const u32 dynb = smem_u32(dsm);
    const u32 pad = (1024u - (dynb & 1023u)) & 1023u;
    char* tb = dsm + pad;
    const u32 tbu = dynb + pad;

    // ---- fill staging (global -> regs -> smem, split across two phases) ----
    const int frow = tid >> 1;          // 0..127 tile row
    const int cb = (tid & 1) << 6;      // byte offset within 128B row (pre path)
    const int seg = (tid & 1) << 5;     // float offset (fp32 path)

    uint4 fa[8], fb[8];                 // staged: [0..3] hi, [4..7] lo
    float4 faf[8];                      // staged fp32 A (when !APRE)

    auto gload = [&](int t) {
        const int k0 = t * 64;
        const size_t aoff = (size_t)z * sA + (size_t)m0 * lda + k0;
        const size_t boff = (size_t)z * sB + (size_t)n0 * ldb + k0;
        if (APRE) {
            const char* gh = (const char*)(Ah + aoff) + (size_t)frow * lda * 2 + cb;
            const char* gl = (const char*)(Al + aoff) + (size_t)frow * lda * 2 + cb;
#pragma unroll
            for (int i = 0; i < 4; ++i) {
                fa[i]     = *(const uint4*)(gh + i * 16);
                fa[4 + i] = *(const uint4*)(gl + i * 16);
            }
        } else {
            const float4* g = (const float4*)(Af + aoff + (size_t)frow * lda + seg);
#pragma unroll
            for (int i = 0; i < 8; ++i) faf[i] = g[i];
        }
        const char* bh = (const char*)(Bh + boff) + (size_t)frow * ldb * 2 + cb;
        const char* bl = (const char*)(Bl + boff) + (size_t)frow * ldb * 2 + cb;
#pragma unroll
        for (int i = 0; i < 4; ++i) {
            fb[i]     = *(const uint4*)(bh + i * 16);
            fb[4 + i] = *(const uint4*)(bl + i * 16);
        }
    };
    auto sstore = [&](int buf) {
        char* ahi = tb + (buf * 4 + 0) * 16384;
        char* alo = tb + (buf * 4 + 1) * 16384;
        char* bhi = tb + (buf * 4 + 2) * 16384;
        char* blo = tb + (buf * 4 + 3) * 16384;
        if (APRE) {
            const u32 rb = frow * 128 + cb;
#pragma unroll
            for (int i = 0; i < 4; ++i) {
                const u32 so = SW128(rb + i * 16);
                *(uint4*)(ahi + so) = fa[i];
                *(uint4*)(alo + so) = fa[4 + i];
            }
        } else {
            const u32 rb = frow * 128 + seg * 2;
#pragma unroll
            for (int i = 0; i < 8; ++i) {
                float4 v = faf[i];
                __nv_bfloat16 h0 = __float2bfloat16_rn(v.x);
                __nv_bfloat16 h1 = __float2bfloat16_rn(v.y);
                __nv_bfloat16 h2 = __float2bfloat16_rn(v.z);
                __nv_bfloat16 h3 = __float2bfloat16_rn(v.w);
                uint2 hp, lp;
                hp.x = pack_bf2(h0, h1);
                hp.y = pack_bf2(h2, h3);
                lp.x = pack_bf2(__float2bfloat16_rn(v.x - __bfloat162float(h0)),
                                __float2bfloat16_rn(v.y - __bfloat162float(h1)));
                lp.y = pack_bf2(__float2bfloat16_rn(v.z - __bfloat162float(h2)),
                                __float2bfloat16_rn(v.w - __bfloat162float(h3)));
                const u32 so = SW128(rb + i * 8);
                *(uint2*)(ahi + so) = hp;
                *(uint2*)(alo + so) = lp;
            }
        }
        const u32 rb = frow * 128 + cb;
#pragma unroll
        for (int i = 0; i < 4; ++i) {
            const u32 so = SW128(rb + i * 16);
            *(uint4*)(bhi + so) = fb[i];
            *(uint4*)(blo + so) = fb[4 + i];
        }
    };

    // ---- warp / lane geometry ----
    const int lane = tid & 31;
    const int w = tid >> 5;
    const int wm = (w & 3) * 32;        // warp m offset (4 warps in m)
    const int wn = (w >> 2) * 64;       // warp n offset (2 warps in n)
    // ldmatrix lane address components
    const int arow = (((lane >> 3) & 1) << 3) + (lane & 7);   // A: m within tile
    const int akof = (lane >> 4) << 3;                        // A: k offset
    const int brow = ((lane >> 4) << 3) + (lane & 7);         // B: n within pair
    const int bkof = ((lane >> 3) & 1) << 3;                  // B: k offset

    float acc[2][8][4];
#pragma unroll
    for (int mt = 0; mt < 2; ++mt)
#pragma unroll
        for (int nt = 0; nt < 8; ++nt)
#pragma unroll
            for (int i = 0; i < 4; ++i) acc[mt][nt][i] = 0.f;

    auto compute = [&](int buf) {
        const u32 a_hi = tbu + (buf * 4 + 0) * 16384;
        const u32 a_lo = tbu + (buf * 4 + 1) * 16384;
        const u32 b_hi = tbu + (buf * 4 + 2) * 16384;
        const u32 b_lo = tbu + (buf * 4 + 3) * 16384;
#pragma unroll
        for (int ks = 0; ks < 4; ++ks) {
            const int kk = ks * 16;
            u32 Ahf[2][4], Alf[2][4];
#pragma unroll
            for (int mt = 0; mt < 2; ++mt) {
                const u32 off = SW128((u32)((wm + mt * 16 + arow) * 128 + (kk + akof) * 2));
                ldm4(Ahf[mt][0], Ahf[mt][1], Ahf[mt][2], Ahf[mt][3], a_hi + off);
                ldm4(Alf[mt][0], Alf[mt][1], Alf[mt][2], Alf[mt][3], a_lo + off);
            }
#pragma unroll
            for (int np = 0; np < 4; ++np) {
                const u32 off = SW128((u32)((wn + np * 16 + brow) * 128 + (kk + bkof) * 2));
                u32 bh0, bh1, bh2, bh3, bl0, bl1, bl2, bl3;
                ldm4(bh0, bh1, bh2, bh3, b_hi + off);
                ldm4(bl0, bl1, bl2, bl3, b_lo + off);
#pragma unroll
                for (int mt = 0; mt < 2; ++mt) {
                    float* d0 = acc[mt][np * 2 + 0];
                    float* d1 = acc[mt][np * 2 + 1];
                    mma_bf16(d0, Ahf[mt], bh0, bh1);
                    mma_bf16(d0, Ahf[mt], bl0, bl1);
                    mma_bf16(d0, Alf[mt], bh0, bh1);
                    mma_bf16(d1, Ahf[mt], bh2, bh3);
                    mma_bf16(d1, Ahf[mt], bl2, bl3);
                    mma_bf16(d1, Alf[mt], bh2, bh3);
                }
            }
        }
    };

    gload(0);
    sstore(0);
    __syncthreads();

    const int nT = Kdim >> 6;
    int cur = 0;
    for (int t = 0; t < nT; ++t) {
        if (t + 1 < nT) gload(t + 1);
        compute(cur);
        if (t + 1 < nT) sstore(cur ^ 1);
        __syncthreads();
        cur ^= 1;
    }

    // ---- epilogue: registers -> global ----
#pragma unroll
    for (int mt = 0; mt < 2; ++mt) {
#pragma unroll
        for (int nt = 0; nt < 8; ++nt) {
            const int mr = m0 + wm + mt * 16 + (lane >> 2);
            const int nc = n0 + wn + nt * 8 + (lane & 3) * 2;
            float v0 = acc[mt][nt][0], v1 = acc[mt][nt][1];
            float v2 = acc[mt][nt][2], v3 = acc[mt][nt][3];
            if (EPI == 1) { v0 *= scale; v1 *= scale; v2 *= scale; v3 *= scale; }
            if (EPI == 0 || EPI == 2) {
                const float b0 = bias[nc], b1 = bias[nc + 1];
                v0 += b0; v1 += b1; v2 += b0; v3 += b1;
            }
            if (EPI == 2) {
                __nv_bfloat16 h0 = __float2bfloat16_rn(v0);
                __nv_bfloat16 h1 = __float2bfloat16_rn(v1);
                __nv_bfloat16 h2 = __float2bfloat16_rn(v2);
                __nv_bfloat16 h3 = __float2bfloat16_rn(v3);
                const size_t o0 = (size_t)z * sC + (size_t)mr * ldc + nc;
                const size_t o1 = (size_t)z * sC + (size_t)(mr + 8) * ldc + nc;
                *(u32*)(Ch + o0) = pack_bf2(h0, h1);
                *(u32*)(Ch + o1) = pack_bf2(h2, h3);
                *(u32*)(Cl + o0) = pack_bf2(__float2bfloat16_rn(v0 - __bfloat162float(h0)),
                                            __float2bfloat16_rn(v1 - __bfloat162float(h1)));
                *(u32*)(Cl + o1) = pack_bf2(__float2bfloat16_rn(v2 - __bfloat162float(h2)),
                                            __float2bfloat16_rn(v3 - __bfloat162float(h3)));
            } else {
                float* c0 = Cf + (size_t)z * sC + (size_t)mr * ldc + nc;
                float* c1 = Cf + (size_t)z * sC + (size_t)(mr + 8) * ldc + nc;
                *(float2*)c0 = make_float2(v0, v1);
                *(float2*)c1 = make_float2(v2, v3);
            }
        }
    }
}

// ---------------- transpose + bf16 split: out[c][r] = split(in[r][c]) ----------------
__global__ __launch_bounds__(256) void transpose_split_k(
    const float* __restrict__ in, __nv_bfloat16* __restrict__ oh,
    __nv_bfloat16* __restrict__ ol, int R, int C,
    long long sIn, long long sOut)
{
    __shared__ float tile[32][33];
    const long long z = blockIdx.z;
    in += z * sIn; oh += z * sOut; ol += z * sOut;
    const int c0 = blockIdx.x * 32, r0 = blockIdx.y * 32;
    const int tx = threadIdx.x, ty = threadIdx.y;
#pragma unroll
    for (int j = 0; j < 32; j += 8)
        tile[ty + j][tx] = in[(size_t)(r0 + ty + j) * C + c0 + tx];
    __syncthreads();
#pragma unroll
    for (int j = 0; j < 32; j += 8) {
        float f = tile[tx][ty + j];
        __nv_bfloat16 h = __float2bfloat16_rn(f);
        __nv_bfloat16 l = __float2bfloat16_rn(f - __bfloat162float(h));
        size_t o = (size_t)(c0 + ty + j) * R + r0 + tx;
        oh[o] = h;
        ol[o] = l;
    }
}

// ---------------- row softmax over 4096 cols, output split bf16 planes ----------------
__global__ __launch_bounds__(256) void softmax_split_k(
    const float* __restrict__ S, __nv_bfloat16* __restrict__ Ph,
    __nv_bfloat16* __restrict__ Pl)
{
    const size_t row = blockIdx.x;
    const float4* p = reinterpret_cast<const float4*>(S + (row << 12));
    uint2* oh = reinterpret_cast<uint2*>(Ph + (row << 12));
    uint2* ol = reinterpret_cast<uint2*>(Pl + (row << 12));
    const int tid = threadIdx.x;

    float4 v[4];
#pragma unroll
    for (int r = 0; r < 4; ++r) v[r] = p[tid + (r << 8)];

    float m = v[0].x;
#pragma unroll
    for (int r = 0; r < 4; ++r) {
        m = fmaxf(m, v[r].x); m = fmaxf(m, v[r].y);
        m = fmaxf(m, v[r].z); m = fmaxf(m, v[r].w);
    }
#pragma unroll
    for (int o = 16; o > 0; o >>= 1) m = fmaxf(m, __shfl_xor_sync(0xffffffffu, m, o));

    __shared__ float red[8];
    if ((tid & 31) == 0) red[tid >> 5] = m;
    __syncthreads();
    m = red[0];
#pragma unroll
    for (int i = 1; i < 8; ++i) m = fmaxf(m, red[i]);
    __syncthreads();

    float s = 0.f;
#pragma unroll
    for (int r = 0; r < 4; ++r) {
        v[r].x = __expf(v[r].x - m); s += v[r].x;
        v[r].y = __expf(v[r].y - m); s += v[r].y;
        v[r].z = __expf(v[r].z - m); s += v[r].z;
        v[r].w = __expf(v[r].w - m); s += v[r].w;
    }
#pragma unroll
    for (int o = 16; o > 0; o >>= 1) s += __shfl_xor_sync(0xffffffffu, s, o);
    if ((tid & 31) == 0) red[tid >> 5] = s;
    __syncthreads();
    s = 0.f;
#pragma unroll
    for (int i = 0; i < 8; ++i) s += red[i];

    const float inv = 1.0f / s;
#pragma unroll
    for (int r = 0; r < 4; ++r) {
        float f0 = v[r].x * inv, f1 = v[r].y * inv;
        float f2 = v[r].z * inv, f3 = v[r].w * inv;
        __nv_bfloat16 h0 = __float2bfloat16_rn(f0);
        __nv_bfloat16 h1 = __float2bfloat16_rn(f1);
        __nv_bfloat16 h2 = __float2bfloat16_rn(f2);
        __nv_bfloat16 h3 = __float2bfloat16_rn(f3);
        uint2 hp, lp;
        hp.x = pack_bf2(h0, h1);
        hp.y = pack_bf2(h2, h3);
        lp.x = pack_bf2(__float2bfloat16_rn(f0 - __bfloat162float(h0)),
                        __float2bfloat16_rn(f1 - __bfloat162float(h1)));
        lp.y = pack_bf2(__float2bfloat16_rn(f2 - __bfloat162float(h2)),
                        __float2bfloat16_rn(f3 - __bfloat162float(h3)));
        oh[tid + (r << 8)] = hp;
        ol[tid + (r << 8)] = lp;
    }
}

// ---------------- launch ----------------
extern "C" void kernel_launch(void* const* d_in, const int* in_sizes, int n_in,
                              void* d_out, int out_size)
{
    (void)in_sizes; (void)n_in; (void)out_size;
    const float* X  = (const float*)d_in[0];
    const float* Wq = (const float*)d_in[1];
    const float* bq = (const float*)d_in[2];
    const float* Wk = (const float*)d_in[3];
    const float* bk = (const float*)d_in[4];
    const float* Wv = (const float*)d_in[5];
    const float* bv = (const float*)d_in[6];
    float* out = (float*)d_out;

    float *Vp, *Sp;
    __nv_bfloat16 *Qh, *Ql, *Kh, *Kl, *Sh, *Sl, *WTh, *WTl, *VTh, *VTl;
    cudaGetSymbolAddress((void**)&Vp,  g_V);
    cudaGetSymbolAddress((void**)&Sp,  g_S);
    cudaGetSymbolAddress((void**)&Qh,  g_Qh);
    cudaGetSymbolAddress((void**)&Ql,  g_Ql);
    cudaGetSymbolAddress((void**)&Kh,  g_Kh);
    cudaGetSymbolAddress((void**)&Kl,  g_Kl);
    cudaGetSymbolAddress((void**)&Sh,  g_Sh);
    cudaGetSymbolAddress((void**)&Sl,  g_Sl);
    cudaGetSymbolAddress((void**)&WTh, g_WTh);
    cudaGetSymbolAddress((void**)&WTl, g_WTl);
    cudaGetSymbolAddress((void**)&VTh, g_VTh);
    cudaGetSymbolAddress((void**)&VTl, g_VTl);

    cudaFuncSetAttribute(tgemm<false, 2>, cudaFuncAttributeMaxDynamicSharedMemorySize, TGEMM_SMEM);
    cudaFuncSetAttribute(tgemm<false, 0>, cudaFuncAttributeMaxDynamicSharedMemorySize, TGEMM_SMEM);
    cudaFuncSetAttribute(tgemm<true,  1>, cudaFuncAttributeMaxDynamicSharedMemorySize, TGEMM_SMEM);
    cudaFuncSetAttribute(tgemm<true,  3>, cudaFuncAttributeMaxDynamicSharedMemorySize, TGEMM_SMEM);

    const float scale = 0.04419417382415922f;  // 1/sqrt(512)
    dim3 blk(256);
    dim3 tblk(32, 8);

    // 1) transpose+split weights: W[in][out] -> plane[out][in]
    dim3 gtw(HID / 32, HID / 32, 1);
    transpose_split_k<<<gtw, tblk>>>(Wq, WTh + 0 * HID * HID, WTl + 0 * HID * HID, HID, HID, 0, 0);
    transpose_split_k<<<gtw, tblk>>>(Wk, WTh + 1 * HID * HID, WTl + 1 * HID * HID, HID, HID, 0, 0);
    transpose_split_k<<<gtw, tblk>>>(Wv, WTh + 2 * HID * HID, WTl + 2 * HID * HID, HID, HID, 0, 0);

    // 2) projections: M=16384, N=512, K=512. Q,K -> split planes; V -> fp32
    dim3 g1(HID / 128, (BATCH * SEQ) / 128, 1);
    tgemm<false, 2><<<g1, blk, TGEMM_SMEM>>>(
        X, nullptr, nullptr, WTh + 0 * HID * HID, WTl + 0 * HID * HID, bq,
        nullptr, Qh, Ql, HID, HID, HID, HID, 0, 0, 0, 1.f);
    tgemm<false, 2><<<g1, blk, TGEMM_SMEM>>>(
        X, nullptr, nullptr, WTh + 1 * HID * HID, WTl + 1 * HID * HID, bk,
        nullptr, Kh, Kl, HID, HID, HID, HID, 0, 0, 0, 1.f);
    tgemm<false, 0><<<g1, blk, TGEMM_SMEM>>>(
        X, nullptr, nullptr, WTh + 2 * HID * HID, WTl + 2 * HID * HID, bv,
        Vp, nullptr, nullptr, HID, HID, HID, HID, 0, 0, 0, 1.f);

    // 3) transpose+split V: [seq][hid] -> plane[hid][seq], per batch
    dim3 gtv(HID / 32, SEQ / 32, BATCH);
    transpose_split_k<<<gtv, tblk>>>(Vp, VTh, VTl, SEQ, HID,
                                     (long long)SEQ * HID, (long long)HID * SEQ);

    // 4) scores = scale * Q @ K^T  (both operands pre-split)
    dim3 g2(SEQ / 128, SEQ / 128, BATCH);
    tgemm<true, 1><<<g2, blk, TGEMM_SMEM>>>(
        nullptr, Qh, Ql, Kh, Kl, nullptr, Sp, nullptr, nullptr,
        HID, HID, HID, SEQ,
        (long long)SEQ * HID, (long long)SEQ * HID, (long long)SEQ * SEQ, scale);

    // 5) softmax -> split bf16 planes
    softmax_split_k<<<BATCH * SEQ, blk>>>(Sp, Sh, Sl);

    // 6) out = P @ V  (both operands pre-split)
    dim3 g3(HID / 128, SEQ / 128, BATCH);
    tgemm<true, 3><<<g3, blk, TGEMM_SMEM>>>(
        nullptr, Sh, Sl, VTh, VTl, nullptr, out, nullptr, nullptr,
        SEQ, SEQ, SEQ, HID,
        (long long)SEQ * SEQ, (long long)HID * SEQ, (long long)SEQ * HID, 1.f);
}

// round 11
// speedup vs baseline: 2.8649x; 1.1385x over previous
#include <cuda_runtime.h>
#include <cuda_bf16.h>
#include <cstdint>

typedef unsigned int u32;
typedef unsigned long long u64;

#define BATCH 4
#define SEQ   4096
#define HID   512

// ---------------- scratch (no allocations allowed) ----------------
__device__ float g_V[BATCH * SEQ * HID];                    // fp32 V (pre-transpose)
__device__ float g_S[(size_t)BATCH * SEQ * SEQ];            // fp32 scores, 268 MB
__device__ __nv_bfloat16 g_Xh[BATCH * SEQ * HID];           // X hi plane [seq][hid]
__device__ __nv_bfloat16 g_Xl[BATCH * SEQ * HID];
__device__ __nv_bfloat16 g_Qh[BATCH * SEQ * HID];           // Q hi plane [seq][hid]
__device__ __nv_bfloat16 g_Ql[BATCH * SEQ * HID];
__device__ __nv_bfloat16 g_Kh[BATCH * SEQ * HID];           // K hi plane [seq][hid]
__device__ __nv_bfloat16 g_Kl[BATCH * SEQ * HID];
__device__ __nv_bfloat16 g_Sh[(size_t)BATCH * SEQ * SEQ];   // P hi plane, 134 MB
__device__ __nv_bfloat16 g_Sl[(size_t)BATCH * SEQ * SEQ];   // P lo plane, 134 MB
__device__ __nv_bfloat16 g_WTh[3 * HID * HID];              // W^T hi planes [out][in]
__device__ __nv_bfloat16 g_WTl[3 * HID * HID];
__device__ __nv_bfloat16 g_VTh[BATCH * HID * SEQ];          // V^T hi planes [hid][seq]
__device__ __nv_bfloat16 g_VTl[BATCH * HID * SEQ];

// ---------------- helpers ----------------
__device__ __forceinline__ u32 smem_u32(const void* p) {
    u32 a;
    asm("{ .reg .u64 t; cvta.to.shared.u64 t, %1; cvt.u32.u64 %0, t; }" : "=r"(a) : "l"(p));
    return a;
}

#define SW128(o) ((o) ^ (((o) >> 3) & 0x70))

#define CP16(dst, src) \
    asm volatile("cp.async.cg.shared.global [%0], [%1], 16;" :: "r"(dst), "l"(src) : "memory")
#define CP_COMMIT() asm volatile("cp.async.commit_group;" ::: "memory")
#define CP_WAIT0()  asm volatile("cp.async.wait_group 0;" ::: "memory")

__device__ __forceinline__ u32 pack_bf2(__nv_bfloat16 a, __nv_bfloat16 b) {
    return (u32)__bfloat16_as_ushort(a) | ((u32)__bfloat16_as_ushort(b) << 16);
}

__device__ __forceinline__ void ldm4(u32& r0, u32& r1, u32& r2, u32& r3, u32 addr) {
    asm volatile("ldmatrix.sync.aligned.m8n8.x4.shared.b16 {%0,%1,%2,%3}, [%4];"
                 : "=r"(r0), "=r"(r1), "=r"(r2), "=r"(r3) : "r"(addr));
}

__device__ __forceinline__ void mma_bf16(float* d, const u32* a, u32 b0, u32 b1) {
    asm volatile(
        "mma.sync.aligned.m16n8k16.row.col.f32.bf16.bf16.f32 "
        "{%0,%1,%2,%3}, {%4,%5,%6,%7}, {%8,%9}, {%0,%1,%2,%3};"
        : "+f"(d[0]), "+f"(d[1]), "+f"(d[2]), "+f"(d[3])
        : "r"(a[0]), "r"(a[1]), "r"(a[2]), "r"(a[3]), "r"(b0), "r"(b1));
}

// ---------------- HMMA split-bf16 GEMM (all operands pre-split) ----------------
// D[M,N] = A[M,K] @ B[N,K]^T  fp32-equivalent via 3-pass bf16 split.
// CTA tile 128x128, K-chunk 64 (SW128 128B rows), double-buffered cp.async fills.
// 512 threads = 16 warps in 4(m) x 4(n); warp tile 32x32.
// EPI: 0 = fp32 + bias, 1 = fp32 * scale, 2 = split hi/lo planes + bias, 3 = fp32
static constexpr int TGEMM_SMEM = 1024 + 8 * 16384;   // pad + 2 bufs x 4 tiles x 16KB

template <int EPI>
__global__ __launch_bounds__(512, 1) void tgemm(
    const __nv_bfloat16* __restrict__ Ah, const __nv_bfloat16* __restrict__ Al,
    const __nv_bfloat16* __restrict__ Bh, const __nv_bfloat16* __restrict__ Bl,
    const float* __restrict__ bias,
    float* __restrict__ Cf,
    __nv_bfloat16* __restrict__ Ch, __nv_bfloat16* __restrict__ Cl,
    int Kdim, int lda, int ldb, int ldc,
    long long sA, long long sB, long long sC, float scale)
{
    extern __shared__ char dsm[];

    const int tid = threadIdx.x;
    const long long z = blockIdx.z;
    const int m0 = blockIdx.y * 128, n0 = blockIdx.x * 128;

    const u32 dynb = smem_u32(dsm);
    const u32 pad = (1024u - (dynb & 1023u)) & 1023u;
    const u32 tbu = dynb + pad;

    // ---- cp.async fill: 4 tiles x 16KB per buffer; each thread 8 x 16B ----
    const int frow = tid >> 2;              // 0..127 tile row
    const int cbb = (tid & 3) * 32;         // byte offset within 128B row

    auto fill = [&](int t, int buf) {
        const int k0 = t * 64;
        const char* ga  = (const char*)(Ah + (size_t)z * sA + (size_t)(m0 + frow) * lda + k0) + cbb;
        const char* gal = (const char*)(Al + (size_t)z * sA + (size_t)(m0 + frow) * lda + k0) + cbb;
        const char* gb  = (const char*)(Bh + (size_t)z * sB + (size_t)(n0 + frow) * ldb + k0) + cbb;
        const char* gbl = (const char*)(Bl + (size_t)z * sB + (size_t)(n0 + frow) * ldb + k0) + cbb;
        const u32 so0 = SW128((u32)(frow * 128 + cbb));
        const u32 so1 = SW128((u32)(frow * 128 + cbb + 16));
        const u32 base = tbu + (u32)buf * 4 * 16384;
        CP16(base + so0, ga);             CP16(base + so1, ga + 16);
        CP16(base + 16384 + so0, gal);    CP16(base + 16384 + so1, gal + 16);
        CP16(base + 32768 + so0, gb);     CP16(base + 32768 + so1, gb + 16);
        CP16(base + 49152 + so0, gbl);    CP16(base + 49152 + so1, gbl + 16);
    };

    // ---- warp / lane geometry: 16 warps as 4(m) x 4(n), warp tile 32x32 ----
    const int lane = tid & 31;
    const int w = tid >> 5;
    const int wm = (w & 3) * 32;
    const int wn = (w >> 2) * 32;
    const int arow = (((lane >> 3) & 1) << 3) + (lane & 7);   // A: m within 16x16 tile
    const int akof = (lane >> 4) << 3;                        // A: k offset
    const int brow = ((lane >> 4) << 3) + (lane & 7);         // B: n within 16-col pair
    const int bkof = ((lane >> 3) & 1) << 3;                  // B: k offset

    float acc[2][4][4];
#pragma unroll
    for (int mt = 0; mt < 2; ++mt)
#pragma unroll
        for (int nt = 0; nt < 4; ++nt)
#pragma unroll
            for (int i = 0; i < 4; ++i) acc[mt][nt][i] = 0.f;

    auto compute = [&](int buf) {
        const u32 a_hi = tbu + (u32)(buf * 4 + 0) * 16384;
        const u32 a_lo = tbu + (u32)(buf * 4 + 1) * 16384;
        const u32 b_hi = tbu + (u32)(buf * 4 + 2) * 16384;
        const u32 b_lo = tbu + (u32)(buf * 4 + 3) * 16384;
#pragma unroll
        for (int ks = 0; ks < 4; ++ks) {
            const int kk = ks * 16;
            u32 Ahf[2][4], Alf[2][4];
#pragma unroll
            for (int mt = 0; mt < 2; ++mt) {
                const u32 off = SW128((u32)((wm + mt * 16 + arow) * 128 + (kk + akof) * 2));
                ldm4(Ahf[mt][0], Ahf[mt][1], Ahf[mt][2], Ahf[mt][3], a_hi + off);
                ldm4(Alf[mt][0], Alf[mt][1], Alf[mt][2], Alf[mt][3], a_lo + off);
            }
#pragma unroll
            for (int np = 0; np < 2; ++np) {
                const u32 off = SW128((u32)((wn + np * 16 + brow) * 128 + (kk + bkof) * 2));
                u32 bh0, bh1, bh2, bh3, bl0, bl1, bl2, bl3;
                ldm4(bh0, bh1, bh2, bh3, b_hi + off);
                ldm4(bl0, bl1, bl2, bl3, b_lo + off);
#pragma unroll
                for (int mt = 0; mt < 2; ++mt) {
                    float* d0 = acc[mt][np * 2 + 0];
                    float* d1 = acc[mt][np * 2 + 1];
                    mma_bf16(d0, Ahf[mt], bh0, bh1);
                    mma_bf16(d0, Ahf[mt], bl0, bl1);
                    mma_bf16(d0, Alf[mt], bh0, bh1);
                    mma_bf16(d1, Ahf[mt], bh2, bh3);
                    mma_bf16(d1, Ahf[mt], bl2, bl3);
                    mma_bf16(d1, Alf[mt], bh2, bh3);
                }
            }
        }
    };

    fill(0, 0);
    CP_COMMIT();
    CP_WAIT0();
    __syncthreads();

    const int nT = Kdim >> 6;
    int cur = 0;
    for (int t = 0; t < nT; ++t) {
        if (t + 1 < nT) { fill(t + 1, cur ^ 1); CP_COMMIT(); }
        compute(cur);
        if (t + 1 < nT) CP_WAIT0();
        __syncthreads();
        cur ^= 1;
    }

    // ---- epilogue: registers -> global ----
#pragma unroll
    for (int mt = 0; mt < 2; ++mt) {
#pragma unroll
        for (int nt = 0; nt < 4; ++nt) {
            const int mr = m0 + wm + mt * 16 + (lane >> 2);
            const int nc = n0 + wn + nt * 8 + (lane & 3) * 2;
            float v0 = acc[mt][nt][0], v1 = acc[mt][nt][1];
            float v2 = acc[mt][nt][2], v3 = acc[mt][nt][3];
            if (EPI == 1) { v0 *= scale; v1 *= scale; v2 *= scale; v3 *= scale; }
            if (EPI == 0 || EPI == 2) {
                const float b0 = bias[nc], b1 = bias[nc + 1];
                v0 += b0; v1 += b1; v2 += b0; v3 += b1;
            }
            if (EPI == 2) {
                __nv_bfloat16 h0 = __float2bfloat16_rn(v0);
                __nv_bfloat16 h1 = __float2bfloat16_rn(v1);
                __nv_bfloat16 h2 = __float2bfloat16_rn(v2);
                __nv_bfloat16 h3 = __float2bfloat16_rn(v3);
                const size_t o0 = (size_t)z * sC + (size_t)mr * ldc + nc;
                const size_t o1 = (size_t)z * sC + (size_t)(mr + 8) * ldc + nc;
                *(u32*)(Ch + o0) = pack_bf2(h0, h1);
                *(u32*)(Ch + o1) = pack_bf2(h2, h3);
                *(u32*)(Cl + o0) = pack_bf2(__float2bfloat16_rn(v0 - __bfloat162float(h0)),
                                            __float2bfloat16_rn(v1 - __bfloat162float(h1)));
                *(u32*)(Cl + o1) = pack_bf2(__float2bfloat16_rn(v2 - __bfloat162float(h2)),
                                            __float2bfloat16_rn(v3 - __bfloat162float(h3)));
            } else {
                float* c0 = Cf + (size_t)z * sC + (size_t)mr * ldc + nc;
                float* c1 = Cf + (size_t)z * sC + (size_t)(mr + 8) * ldc + nc;
                *(float2*)c0 = make_float2(v0, v1);
                *(float2*)c1 = make_float2(v2, v3);
            }
        }
    }
}

// ---------------- elementwise bf16 split (no transpose): X -> Xh, Xl ----------------
__global__ __launch_bounds__(256) void split_k(
    const float* __restrict__ in, __nv_bfloat16* __restrict__ oh,
    __nv_bfloat16* __restrict__ ol)
{
    const size_t i = ((size_t)blockIdx.x * 256 + threadIdx.x) * 4;
    float4 v = *(const float4*)(in + i);
    __nv_bfloat16 h0 = __float2bfloat16_rn(v.x);
    __nv_bfloat16 h1 = __float2bfloat16_rn(v.y);
    __nv_bfloat16 h2 = __float2bfloat16_rn(v.z);
    __nv_bfloat16 h3 = __float2bfloat16_rn(v.w);
    uint2 hp, lp;
    hp.x = pack_bf2(h0, h1);
    hp.y = pack_bf2(h2, h3);
    lp.x = pack_bf2(__float2bfloat16_rn(v.x - __bfloat162float(h0)),
                    __float2bfloat16_rn(v.y - __bfloat162float(h1)));
    lp.y = pack_bf2(__float2bfloat16_rn(v.z - __bfloat162float(h2)),
                    __float2bfloat16_rn(v.w - __bfloat162float(h3)));
    *(uint2*)(oh + i) = hp;
    *(uint2*)(ol + i) = lp;
}

// ---------------- transpose + bf16 split: out[c][r] = split(in[r][c]) ----------------
__global__ __launch_bounds__(256) void transpose_split_k(
    const float* __restrict__ in, __nv_bfloat16* __restrict__ oh,
    __nv_bfloat16* __restrict__ ol, int R, int C,
    long long sIn, long long sOut)
{
    __shared__ float tile[32][33];
    const long long z = blockIdx.z;
    in += z * sIn; oh += z * sOut; ol += z * sOut;
    const int c0 = blockIdx.x * 32, r0 = blockIdx.y * 32;
    const int tx = threadIdx.x, ty = threadIdx.y;
#pragma unroll
    for (int j = 0; j < 32; j += 8)
        tile[ty + j][tx] = in[(size_t)(r0 + ty + j) * C + c0 + tx];
    __syncthreads();
#pragma unroll
    for (int j = 0; j < 32; j += 8) {
        float f = tile[tx][ty + j];
        __nv_bfloat16 h = __float2bfloat16_rn(f);
        __nv_bfloat16 l = __float2bfloat16_rn(f - __bfloat162float(h));
        size_t o = (size_t)(c0 + ty + j) * R + r0 + tx;
        oh[o] = h;
        ol[o] = l;
    }
}

// ---------------- row softmax over 4096 cols, output split bf16 planes ----------------
__global__ __launch_bounds__(256) void softmax_split_k(
    const float* __restrict__ S, __nv_bfloat16* __restrict__ Ph,
    __nv_bfloat16* __restrict__ Pl)
{
    const size_t row = blockIdx.x;
    const float4* p = reinterpret_cast<const float4*>(S + (row << 12));
    uint2* oh = reinterpret_cast<uint2*>(Ph + (row << 12));
    uint2* ol = reinterpret_cast<uint2*>(Pl + (row << 12));
    const int tid = threadIdx.x;

    float4 v[4];
#pragma unroll
    for (int r = 0; r < 4; ++r) v[r] = p[tid + (r << 8)];

    float m = v[0].x;
#pragma unroll
    for (int r = 0; r < 4; ++r) {
        m = fmaxf(m, v[r].x); m = fmaxf(m, v[r].y);
        m = fmaxf(m, v[r].z); m = fmaxf(m, v[r].w);
    }
#pragma unroll
    for (int o = 16; o > 0; o >>= 1) m = fmaxf(m, __shfl_xor_sync(0xffffffffu, m, o));

    __shared__ float red[8];
    if ((tid & 31) == 0) red[tid >> 5] = m;
    __syncthreads();
    m = red[0];
#pragma unroll
    for (int i = 1; i < 8; ++i) m = fmaxf(m, red[i]);
    __syncthreads();

    float s = 0.f;
#pragma unroll
    for (int r = 0; r < 4; ++r) {
        v[r].x = __expf(v[r].x - m); s += v[r].x;
        v[r].y = __expf(v[r].y - m); s += v[r].y;
        v[r].z = __expf(v[r].z - m); s += v[r].z;
        v[r].w = __expf(v[r].w - m); s += v[r].w;
    }
#pragma unroll
    for (int o = 16; o > 0; o >>= 1) s += __shfl_xor_sync(0xffffffffu, s, o);
    if ((tid & 31) == 0) red[tid >> 5] = s;
    __syncthreads();
    s = 0.f;
#pragma unroll
    for (int i = 0; i < 8; ++i) s += red[i];

    const float inv = 1.0f / s;
#pragma unroll
    for (int r = 0; r < 4; ++r) {
        float f0 = v[r].x * inv, f1 = v[r].y * inv;
        float f2 = v[r].z * inv, f3 = v[r].w * inv;
        __nv_bfloat16 h0 = __float2bfloat16_rn(f0);
        __nv_bfloat16 h1 = __float2bfloat16_rn(f1);
        __nv_bfloat16 h2 = __float2bfloat16_rn(f2);
        __nv_bfloat16 h3 = __float2bfloat16_rn(f3);
        uint2 hp, lp;
        hp.x = pack_bf2(h0, h1);
        hp.y = pack_bf2(h2, h3);
        lp.x = pack_bf2(__float2bfloat16_rn(f0 - __bfloat162float(h0)),
                        __float2bfloat16_rn(f1 - __bfloat162float(h1)));
        lp.y = pack_bf2(__float2bfloat16_rn(f2 - __bfloat162float(h2)),
                        __float2bfloat16_rn(f3 - __bfloat162float(h3)));
        oh[tid + (r << 8)] = hp;
        ol[tid + (r << 8)] = lp;
    }
}

// ---------------- launch ----------------
extern "C" void kernel_launch(void* const* d_in, const int* in_sizes, int n_in,
                              void* d_out, int out_size)
{
    (void)in_sizes; (void)n_in; (void)out_size;
    const float* X  = (const float*)d_in[0];
    const float* Wq = (const float*)d_in[1];
    const float* bq = (const float*)d_in[2];
    const float* Wk = (const float*)d_in[3];
    const float* bk = (const float*)d_in[4];
    const float* Wv = (const float*)d_in[5];
    const float* bv = (const float*)d_in[6];
    float* out = (float*)d_out;

    float *Vp, *Sp;
    __nv_bfloat16 *Xh, *Xl, *Qh, *Ql, *Kh, *Kl, *Sh, *Sl, *WTh, *WTl, *VTh, *VTl;
    cudaGetSymbolAddress((void**)&Vp,  g_V);
    cudaGetSymbolAddress((void**)&Sp,  g_S);
    cudaGetSymbolAddress((void**)&Xh,  g_Xh);
    cudaGetSymbolAddress((void**)&Xl,  g_Xl);
    cudaGetSymbolAddress((void**)&Qh,  g_Qh);
    cudaGetSymbolAddress((void**)&Ql,  g_Ql);
    cudaGetSymbolAddress((void**)&Kh,  g_Kh);
    cudaGetSymbolAddress((void**)&Kl,  g_Kl);
    cudaGetSymbolAddress((void**)&Sh,  g_Sh);
    cudaGetSymbolAddress((void**)&Sl,  g_Sl);
    cudaGetSymbolAddress((void**)&WTh, g_WTh);
    cudaGetSymbolAddress((void**)&WTl, g_WTl);
    cudaGetSymbolAddress((void**)&VTh, g_VTh);
    cudaGetSymbolAddress((void**)&VTl, g_VTl);

    cudaFuncSetAttribute(tgemm<0>, cudaFuncAttributeMaxDynamicSharedMemorySize, TGEMM_SMEM);
    cudaFuncSetAttribute(tgemm<1>, cudaFuncAttributeMaxDynamicSharedMemorySize, TGEMM_SMEM);
    cudaFuncSetAttribute(tgemm<2>, cudaFuncAttributeMaxDynamicSharedMemorySize, TGEMM_SMEM);
    cudaFuncSetAttribute(tgemm<3>, cudaFuncAttributeMaxDynamicSharedMemorySize, TGEMM_SMEM);

    const float scale = 0.04419417382415922f;  // 1/sqrt(512)
    dim3 gblk(512);
    dim3 tblk(32, 8);

    // 1a) split X into bf16 hi/lo planes (elementwise)
    split_k<<<(BATCH * SEQ * HID) / (256 * 4), 256>>>(X, Xh, Xl);

    // 1b) transpose+split weights: W[in][out] -> plane[out][in]
    dim3 gtw(HID / 32, HID / 32, 1);
    transpose_split_k<<<gtw, tblk>>>(Wq, WTh + 0 * HID * HID, WTl + 0 * HID * HID, HID, HID, 0, 0);
    transpose_split_k<<<gtw, tblk>>>(Wk, WTh + 1 * HID * HID, WTl + 1 * HID * HID, HID, HID, 0, 0);
    transpose_split_k<<<gtw, tblk>>>(Wv, WTh + 2 * HID * HID, WTl + 2 * HID * HID, HID, HID, 0, 0);

    // 2) projections: M=16384, N=512, K=512. Q,K -> split planes; V -> fp32
    dim3 g1(HID / 128, (BATCH * SEQ) / 128, 1);
    tgemm<2><<<g1, gblk, TGEMM_SMEM>>>(
        Xh, Xl, WTh + 0 * HID * HID, WTl + 0 * HID * HID, bq,
        nullptr, Qh, Ql, HID, HID, HID, HID, 0, 0, 0, 1.f);
    tgemm<2><<<g1, gblk, TGEMM_SMEM>>>(
        Xh, Xl, WTh + 1 * HID * HID, WTl + 1 * HID * HID, bk,
        nullptr, Kh, Kl, HID, HID, HID, HID, 0, 0, 0, 1.f);
    tgemm<0><<<g1, gblk, TGEMM_SMEM>>>(
        Xh, Xl, WTh + 2 * HID * HID, WTl + 2 * HID * HID, bv,
        Vp, nullptr, nullptr, HID, HID, HID, HID, 0, 0, 0, 1.f);

    // 3) transpose+split V: [seq][hid] -> plane[hid][seq], per batch
    dim3 gtv(HID / 32, SEQ / 32, BATCH);
    transpose_split_k<<<gtv, tblk>>>(Vp, VTh, VTl, SEQ, HID,
                                     (long long)SEQ * HID, (long long)HID * SEQ);

    // 4) scores = scale * Q @ K^T
    dim3 g2(SEQ / 128, SEQ / 128, BATCH);
    tgemm<1><<<g2, gblk, TGEMM_SMEM>>>(
        Qh, Ql, Kh, Kl, nullptr, Sp, nullptr, nullptr,
        HID, HID, HID, SEQ,
        (long long)SEQ * HID, (long long)SEQ * HID, (long long)SEQ * SEQ, scale);

    // 5) softmax -> split bf16 planes
    softmax_split_k<<<BATCH * SEQ, 256>>>(Sp, Sh, Sl);

    // 6) out = P @ V
    dim3 g3(HID / 128, SEQ / 128, BATCH);
    tgemm<3><<<g3, gblk, TGEMM_SMEM>>>(
        Sh, Sl, VTh, VTl, nullptr, out, nullptr, nullptr,
        SEQ, SEQ, SEQ, HID,
        (long long)SEQ * SEQ, (long long)HID * SEQ, (long long)SEQ * HID, 1.f);
}

// round 13
// speedup vs baseline: 2.9446x; 1.0278x over previous
// R13 = R12 resubmission (R12 hit "GB300 container failed twice" infra error;
// no compile/runtime evidence against the kernel itself).
#include <cuda_runtime.h>
#include <cuda_bf16.h>
#include <cstdint>

typedef unsigned int u32;
typedef unsigned long long u64;

#define BATCH 4
#define SEQ   4096
#define HID   512

// ---------------- scratch (no allocations allowed) ----------------
__device__ float g_V[BATCH * SEQ * HID];                    // fp32 V (pre-transpose)
__device__ float g_S[(size_t)BATCH * SEQ * SEQ];            // fp32 scores, 268 MB
__device__ __nv_bfloat16 g_Xh[BATCH * SEQ * HID];           // X hi plane [seq][hid]
__device__ __nv_bfloat16 g_Xl[BATCH * SEQ * HID];
__device__ __nv_bfloat16 g_Qh[BATCH * SEQ * HID];
__device__ __nv_bfloat16 g_Ql[BATCH * SEQ * HID];
__device__ __nv_bfloat16 g_Kh[BATCH * SEQ * HID];
__device__ __nv_bfloat16 g_Kl[BATCH * SEQ * HID];
__device__ __nv_bfloat16 g_Sh[(size_t)BATCH * SEQ * SEQ];   // P hi plane, 134 MB
__device__ __nv_bfloat16 g_Sl[(size_t)BATCH * SEQ * SEQ];   // P lo plane, 134 MB
__device__ __nv_bfloat16 g_WTh[3 * HID * HID];              // W^T hi planes [out][in], QKV stacked
__device__ __nv_bfloat16 g_WTl[3 * HID * HID];
__device__ __nv_bfloat16 g_VTh[BATCH * HID * SEQ];          // V^T hi planes [hid][seq]
__device__ __nv_bfloat16 g_VTl[BATCH * HID * SEQ];

// ---------------- helpers ----------------
__device__ __forceinline__ u32 smem_u32(const void* p) {
    u32 a;
    asm("{ .reg .u64 t; cvta.to.shared.u64 t, %1; cvt.u32.u64 %0, t; }" : "=r"(a) : "l"(p));
    return a;
}

#define SW128(o) ((o) ^ (((o) >> 3) & 0x70))

#define CP16(dst, src) \
    asm volatile("cp.async.cg.shared.global [%0], [%1], 16;" :: "r"(dst), "l"(src) : "memory")
#define CP_COMMIT() asm volatile("cp.async.commit_group;" ::: "memory")
#define CP_WAIT0()  asm volatile("cp.async.wait_group 0;" ::: "memory")

__device__ __forceinline__ u32 pack_bf2(__nv_bfloat16 a, __nv_bfloat16 b) {
    return (u32)__bfloat16_as_ushort(a) | ((u32)__bfloat16_as_ushort(b) << 16);
}

__device__ __forceinline__ void ldm4(u32& r0, u32& r1, u32& r2, u32& r3, u32 addr) {
    asm volatile("ldmatrix.sync.aligned.m8n8.x4.shared.b16 {%0,%1,%2,%3}, [%4];"
                 : "=r"(r0), "=r"(r1), "=r"(r2), "=r"(r3) : "r"(addr));
}

__device__ __forceinline__ void mma_bf16(float* d, const u32* a, u32 b0, u32 b1) {
    asm volatile(
        "mma.sync.aligned.m16n8k16.row.col.f32.bf16.bf16.f32 "
        "{%0,%1,%2,%3}, {%4,%5,%6,%7}, {%8,%9}, {%0,%1,%2,%3};"
        : "+f"(d[0]), "+f"(d[1]), "+f"(d[2]), "+f"(d[3])
        : "r"(a[0]), "r"(a[1]), "r"(a[2]), "r"(a[3]), "r"(b0), "r"(b1));
}

// ---------------- HMMA split-bf16 GEMM (all operands pre-split) ----------------
// D[M,N] = A[M,K] @ B[N,K]^T  fp32-equivalent via 3-pass bf16 split.
// CTA tile 128x256, K-chunk 64 (SW128 128B rows), double-buffered cp.async fills.
// 512 threads = 16 warps in 4(m) x 4(n); warp tile 32x64.
// Buffer layout (96 KB): A_hi 16K | A_lo 16K | B_hi 32K | B_lo 32K
// EPI: 1 = fp32 * scale, 3 = fp32, 4 = merged-QKV routing (Q/K split planes + bias, V fp32 + bias)
static constexpr int BUF_BYTES = 98304;
static constexpr int TGEMM_SMEM = 1024 + 2 * BUF_BYTES;

template <int EPI>
__global__ __launch_bounds__(512, 1) void tgemm(
    const __nv_bfloat16* __restrict__ Ah, const __nv_bfloat16* __restrict__ Al,
    const __nv_bfloat16* __restrict__ Bh, const __nv_bfloat16* __restrict__ Bl,
    const float* __restrict__ bias,  const float* __restrict__ bias2,
    const float* __restrict__ bias3,
    float* __restrict__ Cf,
    __nv_bfloat16* __restrict__ Ch,  __nv_bfloat16* __restrict__ Cl,
    __nv_bfloat16* __restrict__ C2h, __nv_bfloat16* __restrict__ C2l,
    int Kdim, int lda, int ldb, int ldc,
    long long sA, long long sB, long long sC, float scale)
{
    extern __shared__ char dsm[];

    const int tid = threadIdx.x;
    const long long z = blockIdx.z;
    const int m0 = blockIdx.y * 128, n0 = blockIdx.x * 256;

    const u32 dynb = smem_u32(dsm);
    const u32 pad = (1024u - (dynb & 1023u)) & 1023u;
    const u32 tbu = dynb + pad;

    // ---- cp.async fill: A 2x16KB + B 2x32KB per buffer; 12 x CP16 per thread ----
    const int afr = tid >> 2;               // A row 0..127
    const int acb = (tid & 3) * 32;         // A byte offset in 128B row
    const int bfr = tid >> 1;               // B row 0..255
    const int bcb = (tid & 1) * 64;         // B byte offset in 128B row

    auto fill = [&](int t, int buf) {
        const int k0 = t * 64;
        const u32 base = tbu + (u32)buf * BUF_BYTES;
        {
            const char* ga  = (const char*)(Ah + (size_t)z * sA + (size_t)(m0 + afr) * lda + k0) + acb;
            const char* gal = (const char*)(Al + (size_t)z * sA + (size_t)(m0 + afr) * lda + k0) + acb;
            const u32 so0 = SW128((u32)(afr * 128 + acb));
            const u32 so1 = SW128((u32)(afr * 128 + acb + 16));
            CP16(base + so0, ga);              CP16(base + so1, ga + 16);
            CP16(base + 16384 + so0, gal);     CP16(base + 16384 + so1, gal + 16);
        }
        {
            const char* gb  = (const char*)(Bh + (size_t)z * sB + (size_t)(n0 + bfr) * ldb + k0) + bcb;
            const char* gbl = (const char*)(Bl + (size_t)z * sB + (size_t)(n0 + bfr) * ldb + k0) + bcb;
#pragma unroll
            for (int i = 0; i < 4; ++i) {
                const u32 so = SW128((u32)(bfr * 128 + bcb + i * 16));
                CP16(base + 32768 + so, gb + i * 16);
                CP16(base + 65536 + so, gbl + i * 16);
            }
        }
    };

    // ---- warp / lane geometry: 16 warps as 4(m) x 4(n), warp tile 32x64 ----
    const int lane = tid & 31;
    const int w = tid >> 5;
    const int wm = (w & 3) * 32;
    const int wn = (w >> 2) * 64;
    const int arow = (((lane >> 3) & 1) << 3) + (lane & 7);   // A: m within 16x16 tile
    const int akof = (lane >> 4) << 3;                        // A: k offset
    const int brow = ((lane >> 4) << 3) + (lane & 7);         // B: n within 16-col pair
    const int bkof = ((lane >> 3) & 1) << 3;                  // B: k offset

    float acc[2][8][4];
#pragma unroll
    for (int mt = 0; mt < 2; ++mt)
#pragma unroll
        for (int nt = 0; nt < 8; ++nt)
#pragma unroll
            for (int i = 0; i < 4; ++i) acc[mt][nt][i] = 0.f;

    auto compute = [&](int buf) {
        const u32 a_hi = tbu + (u32)buf * BUF_BYTES;
        const u32 a_lo = a_hi + 16384;
        const u32 b_hi = a_hi + 32768;
        const u32 b_lo = a_hi + 65536;
#pragma unroll
        for (int ks = 0; ks < 4; ++ks) {
            const int kk = ks * 16;
            u32 Ahf[2][4], Alf[2][4];
#pragma unroll
            for (int mt = 0; mt < 2; ++mt) {
                const u32 off = SW128((u32)((wm + mt * 16 + arow) * 128 + (kk + akof) * 2));
                ldm4(Ahf[mt][0], Ahf[mt][1], Ahf[mt][2], Ahf[mt][3], a_hi + off);
                ldm4(Alf[mt][0], Alf[mt][1], Alf[mt][2], Alf[mt][3], a_lo + off);
            }
#pragma unroll
            for (int np = 0; np < 4; ++np) {
                const u32 off = SW128((u32)((wn + np * 16 + brow) * 128 + (kk + bkof) * 2));
                u32 bh0, bh1, bh2, bh3, bl0, bl1, bl2, bl3;
                ldm4(bh0, bh1, bh2, bh3, b_hi + off);
                ldm4(bl0, bl1, bl2, bl3, b_lo + off);
#pragma unroll
                for (int mt = 0; mt < 2; ++mt) {
                    float* d0 = acc[mt][np * 2 + 0];
                    float* d1 = acc[mt][np * 2 + 1];
                    mma_bf16(d0, Ahf[mt], bh0, bh1);
                    mma_bf16(d0, Ahf[mt], bl0, bl1);
                    mma_bf16(d0, Alf[mt], bh0, bh1);
                    mma_bf16(d1, Ahf[mt], bh2, bh3);
                    mma_bf16(d1, Ahf[mt], bl2, bl3);
                    mma_bf16(d1, Alf[mt], bh2, bh3);
                }
            }
        }
    };

    fill(0, 0);
    CP_COMMIT();
    CP_WAIT0();
    __syncthreads();

    const int nT = Kdim >> 6;
    int cur = 0;
    for (int t = 0; t < nT; ++t) {
        if (t + 1 < nT) { fill(t + 1, cur ^ 1); CP_COMMIT(); }
        compute(cur);
        if (t + 1 < nT) CP_WAIT0();
        __syncthreads();
        cur ^= 1;
    }

    // ---- epilogue: registers -> global ----
#pragma unroll
    for (int mt = 0; mt < 2; ++mt) {
#pragma unroll
        for (int nt = 0; nt < 8; ++nt) {
            const int mr = m0 + wm + mt * 16 + (lane >> 2);
            const int nc = n0 + wn + nt * 8 + (lane & 3) * 2;
            float v0 = acc[mt][nt][0], v1 = acc[mt][nt][1];
            float v2 = acc[mt][nt][2], v3 = acc[mt][nt][3];
            if (EPI == 1) { v0 *= scale; v1 *= scale; v2 *= scale; v3 *= scale; }
            if (EPI == 1 || EPI == 3) {
                float* c0 = Cf + (size_t)z * sC + (size_t)mr * ldc + nc;
                float* c1 = Cf + (size_t)z * sC + (size_t)(mr + 8) * ldc + nc;
                *(float2*)c0 = make_float2(v0, v1);
                *(float2*)c1 = make_float2(v2, v3);
            }
            if (EPI == 4) {
                const int nloc = nc & 511;
                const float* bp = (nc < 512) ? bias : (nc < 1024) ? bias2 : bias3;
                const float b0 = bp[nloc], b1 = bp[nloc + 1];
                v0 += b0; v1 += b1; v2 += b0; v3 += b1;
                const size_t o0 = (size_t)mr * HID + nloc;
                const size_t o1 = (size_t)(mr + 8) * HID + nloc;
                if (nc < 1024) {
                    __nv_bfloat16* ph = (nc < 512) ? Ch : C2h;
                    __nv_bfloat16* pl = (nc < 512) ? Cl : C2l;
                    __nv_bfloat16 h0 = __float2bfloat16_rn(v0);
                    __nv_bfloat16 h1 = __float2bfloat16_rn(v1);
                    __nv_bfloat16 h2 = __float2bfloat16_rn(v2);
                    __nv_bfloat16 h3 = __float2bfloat16_rn(v3);
                    *(u32*)(ph + o0) = pack_bf2(h0, h1);
                    *(u32*)(ph + o1) = pack_bf2(h2, h3);
                    *(u32*)(pl + o0) = pack_bf2(__float2bfloat16_rn(v0 - __bfloat162float(h0)),
                                                __float2bfloat16_rn(v1 - __bfloat162float(h1)));
                    *(u32*)(pl + o1) = pack_bf2(__float2bfloat16_rn(v2 - __bfloat162float(h2)),
                                                __float2bfloat16_rn(v3 - __bfloat162float(h3)));
                } else {
                    *(float2*)(Cf + o0) = make_float2(v0, v1);
                    *(float2*)(Cf + o1) = make_float2(v2, v3);
                }
            }
        }
    }
}

// ---------------- elementwise bf16 split: X -> Xh, Xl ----------------
__global__ __launch_bounds__(256) void split_k(
    const float* __restrict__ in, __nv_bfloat16* __restrict__ oh,
    __nv_bfloat16* __restrict__ ol)
{
    const size_t i = ((size_t)blockIdx.x * 256 + threadIdx.x) * 4;
    float4 v = *(const float4*)(in + i);
    __nv_bfloat16 h0 = __float2bfloat16_rn(v.x);
    __nv_bfloat16 h1 = __float2bfloat16_rn(v.y);
    __nv_bfloat16 h2 = __float2bfloat16_rn(v.z);
    __nv_bfloat16 h3 = __float2bfloat16_rn(v.w);
    uint2 hp, lp;
    hp.x = pack_bf2(h0, h1);
    hp.y = pack_bf2(h2, h3);
    lp.x = pack_bf2(__float2bfloat16_rn(v.x - __bfloat162float(h0)),
                    __float2bfloat16_rn(v.y - __bfloat162float(h1)));
    lp.y = pack_bf2(__float2bfloat16_rn(v.z - __bfloat162float(h2)),
                    __float2bfloat16_rn(v.w - __bfloat162float(h3)));
    *(uint2*)(oh + i) = hp;
    *(uint2*)(ol + i) = lp;
}

// ---------------- transpose + bf16 split: out[c][r] = split(in[r][c]) ----------------
__global__ __launch_bounds__(256) void transpose_split_k(
    const float* __restrict__ in, __nv_bfloat16* __restrict__ oh,
    __nv_bfloat16* __restrict__ ol, int R, int C,
    long long sIn, long long sOut)
{
    __shared__ float tile[32][33];
    const long long z = blockIdx.z;
    in += z * sIn; oh += z * sOut; ol += z * sOut;
    const int c0 = blockIdx.x * 32, r0 = blockIdx.y * 32;
    const int tx = threadIdx.x, ty = threadIdx.y;
#pragma unroll
    for (int j = 0; j < 32; j += 8)
        tile[ty + j][tx] = in[(size_t)(r0 + ty + j) * C + c0 + tx];
    __syncthreads();
#pragma unroll
    for (int j = 0; j < 32; j += 8) {
        float f = tile[tx][ty + j];
        __nv_bfloat16 h = __float2bfloat16_rn(f);
        __nv_bfloat16 l = __float2bfloat16_rn(f - __bfloat162float(h));
        size_t o = (size_t)(c0 + ty + j) * R + r0 + tx;
        oh[o] = h;
        ol[o] = l;
    }
}

// ---------------- row softmax over 4096 cols, output split bf16 planes ----------------
__global__ __launch_bounds__(256) void softmax_split_k(
    const float* __restrict__ S, __nv_bfloat16* __restrict__ Ph,
    __nv_bfloat16* __restrict__ Pl)
{
    const size_t row = blockIdx.x;
    const float4* p = reinterpret_cast<const float4*>(S + (row << 12));
    uint2* oh = reinterpret_cast<uint2*>(Ph + (row << 12));
    uint2* ol = reinterpret_cast<uint2*>(Pl + (row << 12));
    const int tid = threadIdx.x;

    float4 v[4];
#pragma unroll
    for (int r = 0; r < 4; ++r) v[r] = p[tid + (r << 8)];

    float m = v[0].x;
#pragma unroll
    for (int r = 0; r < 4; ++r) {
        m = fmaxf(m, v[r].x); m = fmaxf(m, v[r].y);
        m = fmaxf(m, v[r].z); m = fmaxf(m, v[r].w);
    }
#pragma unroll
    for (int o = 16; o > 0; o >>= 1) m = fmaxf(m, __shfl_xor_sync(0xffffffffu, m, o));

    __shared__ float red[8];
    if ((tid & 31) == 0) red[tid >> 5] = m;
    __syncthreads();
    m = red[0];
#pragma unroll
    for (int i = 1; i < 8; ++i) m = fmaxf(m, red[i]);
    __syncthreads();

    float s = 0.f;
#pragma unroll
    for (int r = 0; r < 4; ++r) {
        v[r].x = __expf(v[r].x - m); s += v[r].x;
        v[r].y = __expf(v[r].y - m); s += v[r].y;
        v[r].z = __expf(v[r].z - m); s += v[r].z;
        v[r].w = __expf(v[r].w - m); s += v[r].w;
    }
#pragma unroll
    for (int o = 16; o > 0; o >>= 1) s += __shfl_xor_sync(0xffffffffu, s, o);
    if ((tid & 31) == 0) red[tid >> 5] = s;
    __syncthreads();
    s = 0.f;
#pragma unroll
    for (int i = 0; i < 8; ++i) s += red[i];

    const float inv = 1.0f / s;
#pragma unroll
    for (int r = 0; r < 4; ++r) {
        float f0 = v[r].x * inv, f1 = v[r].y * inv;
        float f2 = v[r].z * inv, f3 = v[r].w * inv;
        __nv_bfloat16 h0 = __float2bfloat16_rn(f0);
        __nv_bfloat16 h1 = __float2bfloat16_rn(f1);
        __nv_bfloat16 h2 = __float2bfloat16_rn(f2);
        __nv_bfloat16 h3 = __float2bfloat16_rn(f3);
        uint2 hp, lp;
        hp.x = pack_bf2(h0, h1);
        hp.y = pack_bf2(h2, h3);
        lp.x = pack_bf2(__float2bfloat16_rn(f0 - __bfloat162float(h0)),
                        __float2bfloat16_rn(f1 - __bfloat162float(h1)));
        lp.y = pack_bf2(__float2bfloat16_rn(f2 - __bfloat162float(h2)),
                        __float2bfloat16_rn(f3 - __bfloat162float(h3)));
        oh[tid + (r << 8)] = hp;
        ol[tid + (r << 8)] = lp;
    }
}

// ---------------- launch ----------------
extern "C" void kernel_launch(void* const* d_in, const int* in_sizes, int n_in,
                              void* d_out, int out_size)
{
    (void)in_sizes; (void)n_in; (void)out_size;
    const float* X  = (const float*)d_in[0];
    const float* Wq = (const float*)d_in[1];
    const float* bq = (const float*)d_in[2];
    const float* Wk = (const float*)d_in[3];
    const float* bk = (const float*)d_in[4];
    const float* Wv = (const float*)d_in[5];
    const float* bv = (const float*)d_in[6];
    float* out = (float*)d_out;

    float *Vp, *Sp;
    __nv_bfloat16 *Xh, *Xl, *Qh, *Ql, *Kh, *Kl, *Sh, *Sl, *WTh, *WTl, *VTh, *VTl;
    cudaGetSymbolAddress((void**)&Vp,  g_V);
    cudaGetSymbolAddress((void**)&Sp,  g_S);
    cudaGetSymbolAddress((void**)&Xh,  g_Xh);
    cudaGetSymbolAddress((void**)&Xl,  g_Xl);
    cudaGetSymbolAddress((void**)&Qh,  g_Qh);
    cudaGetSymbolAddress((void**)&Ql,  g_Ql);
    cudaGetSymbolAddress((void**)&Kh,  g_Kh);
    cudaGetSymbolAddress((void**)&Kl,  g_Kl);
    cudaGetSymbolAddress((void**)&Sh,  g_Sh);
    cudaGetSymbolAddress((void**)&Sl,  g_Sl);
    cudaGetSymbolAddress((void**)&WTh, g_WTh);
    cudaGetSymbolAddress((void**)&WTl, g_WTl);
    cudaGetSymbolAddress((void**)&VTh, g_VTh);
    cudaGetSymbolAddress((void**)&VTl, g_VTl);

    cudaFuncSetAttribute(tgemm<1>, cudaFuncAttributeMaxDynamicSharedMemorySize, TGEMM_SMEM);
    cudaFuncSetAttribute(tgemm<3>, cudaFuncAttributeMaxDynamicSharedMemorySize, TGEMM_SMEM);
    cudaFuncSetAttribute(tgemm<4>, cudaFuncAttributeMaxDynamicSharedMemorySize, TGEMM_SMEM);

    const float scale = 0.04419417382415922f;  // 1/sqrt(512)
    dim3 gblk(512);
    dim3 tblk(32, 8);

    // 1a) split X into bf16 hi/lo planes
    split_k<<<(BATCH * SEQ * HID) / (256 * 4), 256>>>(X, Xh, Xl);

    // 1b) transpose+split weights: W[in][out] -> plane[out][in], QKV stacked
    dim3 gtw(HID / 32, HID / 32, 1);
    transpose_split_k<<<gtw, tblk>>>(Wq, WTh + 0 * HID * HID, WTl + 0 * HID * HID, HID, HID, 0, 0);
    transpose_split_k<<<gtw, tblk>>>(Wk, WTh + 1 * HID * HID, WTl + 1 * HID * HID, HID, HID, 0, 0);
    transpose_split_k<<<gtw, tblk>>>(Wv, WTh + 2 * HID * HID, WTl + 2 * HID * HID, HID, HID, 0, 0);

    // 2) merged QKV projection: M=16384, N=1536, K=512
    //    n<512 -> Q split planes, n<1024 -> K split planes, else V fp32
    dim3 g1((3 * HID) / 256, (BATCH * SEQ) / 128, 1);
    tgemm<4><<<g1, gblk, TGEMM_SMEM>>>(
        Xh, Xl, WTh, WTl, bq, bk, bv,
        Vp, Qh, Ql, Kh, Kl,
        HID, HID, HID, HID, 0, 0, 0, 1.f);

    // 3) transpose+split V: [seq][hid] -> plane[hid][seq], per batch
    dim3 gtv(HID / 32, SEQ / 32, BATCH);
    transpose_split_k<<<gtv, tblk>>>(Vp, VTh, VTl, SEQ, HID,
                                     (long long)SEQ * HID, (long long)HID * SEQ);

    // 4) scores = scale * Q @ K^T
    dim3 g2(SEQ / 256, SEQ / 128, BATCH);
    tgemm<1><<<g2, gblk, TGEMM_SMEM>>>(
        Qh, Ql, Kh, Kl, nullptr, nullptr, nullptr,
        Sp, nullptr, nullptr, nullptr, nullptr,
        HID, HID, HID, SEQ,
        (long long)SEQ * HID, (long long)SEQ * HID, (long long)SEQ * SEQ, scale);

    // 5) softmax -> split bf16 planes
    softmax_split_k<<<BATCH * SEQ, 256>>>(Sp, Sh, Sl);

    // 6) out = P @ V
    dim3 g3(HID / 256, SEQ / 128, BATCH);
    tgemm<3><<<g3, gblk, TGEMM_SMEM>>>(
        Sh, Sl, VTh, VTl, nullptr, nullptr, nullptr,
        out, nullptr, nullptr, nullptr, nullptr,
        SEQ, SEQ, SEQ, HID,
        (long long)SEQ * SEQ, (long long)HID * SEQ, (long long)SEQ * HID, 1.f);
}